// round 13
// baseline (speedup 1.0000x reference)
#include <cuda_runtime.h>
#include <cstddef>

// ---------------------------------------------------------------------------
// Differentiable JPEG (quality=75), fused, thread-per-row.  [R11 + occ 7]
// CTA = 64x64 pixel tile = 96 8x8 blocks (64 Y + 32 chroma).
// 256 threads = 32 groups of 8; each group does one block per round (3 rounds).
// Per block: rec = M ( diff_round( (M (X M^T)) / qt ) * qt ) M^T as 4 identical
// 8-pt butterflies, 2 smem transposes. qt + reciprocal: compile-time tables in
// GLOBAL memory, staged to smem (constant-port divergent-LDC replays killed),
// hoisted to registers once per table via conflict-free LDS.
// Division = rcp-mul + one FMA Newton residual (bit-identical rel_err vs FDIV).
// Shared pitch 9/72 -> conflict-free row AND column access.
// Phase purity: load and output phases are pure streaming (R10/R12 showed any
// dct fusion into memory phases serializes and regresses).
// R13 change: __launch_bounds__(256,7) -> 7 CTAs/SM (occ cap 75%, 36-reg cap).
// ---------------------------------------------------------------------------

#define THREADS 256
#define BPITCH 72
#define RPITCH 9

// ---- Compile-time scaled quant tables (quality=75 -> s=50 -> t=(q+1)/2). ----
struct QTab { float q[64]; float r[64]; };
struct QTabs { QTab y; QTab c; };

constexpr QTab make_tab(const int (&b)[64]) {
  QTab t{};
  for (int i = 0; i < 64; i++) {
    int n = b[i] + 1;                       // scaled numerator: t = n/2 exactly
    double v = 0.0;
    if ((n & 1) == 0) {
      v = (double)(n / 2);                  // integer -> diff_round is identity
    } else {
      long k = n / 2;                       // t = k + 0.5 (exact tie)
      double tt = (double)k + 0.5;
      double rr = ((k & 1) == 0) ? (double)k : (double)(k + 1);  // half-to-even
      double d  = tt - rr;
      v = rr + d * d * d;                   // diff_round
    }
    if (v < 1.0) v = 1.0;
    if (v > 255.0) v = 255.0;
    t.q[i] = (float)v;                      // exact (values are k + m/8)
    t.r[i] = (float)(1.0 / (double)((float)v));  // correctly-rounded fp32 recip
  }
  return t;
}

constexpr int QY_B[64] = {
  16,11,10,16,24,40,51,61,
  12,12,14,19,26,58,60,55,
  14,13,16,24,40,57,69,56,
  14,17,22,29,51,87,80,62,
  18,22,37,56,68,109,103,77,
  24,35,55,64,81,104,113,92,
  49,64,78,87,103,121,120,101,
  72,92,95,98,112,100,103,99 };

constexpr int QC_B[64] = {
  17,18,24,47,99,99,99,99,
  18,21,26,66,99,99,99,99,
  24,26,56,99,99,99,99,99,
  47,66,99,99,99,99,99,99,
  99,99,99,99,99,99,99,99,
  99,99,99,99,99,99,99,99,
  99,99,99,99,99,99,99,99,
  99,99,99,99,99,99,99,99 };

// Global memory (not __constant__): divergent LDC replays on the half-rate
// constant port serialized R7/R8.
__device__ const QTabs G_QT = { make_tab(QY_B), make_tab(QC_B) };

__device__ __forceinline__ float diff_round(float x) {
  float r = rintf(x);           // round half to even, matches jnp.round
  float d = x - r;
  return fmaf(d * d, d, r);
}

// out[u] = sum_k M[u,k] a[k] -- 8-pt DCT-II via even/odd butterfly (~36 ops).
__device__ __forceinline__ void dct8(const float* __restrict__ a, float* __restrict__ out) {
  const float S  = 0.3535533905932738f;
  const float A  = 0.4619397662556434f, B  = 0.1913417161825449f;
  const float c1 = 0.4903926402016152f, c3 = 0.4157348061512726f;
  const float c5 = 0.2777851165098011f, c7 = 0.0975451610080641f;
  float e0 = a[0] + a[7], e1 = a[1] + a[6], e2 = a[2] + a[5], e3 = a[3] + a[4];
  float o0 = a[0] - a[7], o1 = a[1] - a[6], o2 = a[2] - a[5], o3 = a[3] - a[4];
  float q0 = e0 + e3, q1 = e1 + e2;
  float r0 = e0 - e3, r1 = e1 - e2;
  out[0] = S * (q0 + q1);
  out[4] = S * (q0 - q1);
  out[2] = fmaf(A, r0,  B * r1);
  out[6] = fmaf(B, r0, -A * r1);
  out[1] = fmaf(c1, o0, fmaf( c3, o1, fmaf( c5, o2,  c7 * o3)));
  out[3] = fmaf(c3, o0, fmaf(-c7, o1, fmaf(-c1, o2, -c5 * o3)));
  out[5] = fmaf(c5, o0, fmaf(-c1, o1, fmaf( c7, o2,  c3 * o3)));
  out[7] = fmaf(c7, o0, fmaf(-c5, o1, fmaf( c3, o2, -c1 * o3)));
}

// Full block pipeline, thread t of an 8-thread group. Only 2 syncwarps.
// qcol/rcol: this thread's quant column (qt[u][t]) and its fp32 reciprocal.
__device__ __forceinline__ void process_block(float* __restrict__ base, int t,
                                              const float* __restrict__ qcol,
                                              const float* __restrict__ rcol) {
  // Pass 1 (row-local): W[t,:] = row t of (X M^T).
  float a[8];
#pragma unroll
  for (int k = 0; k < 8; k++) a[k] = base[t * RPITCH + k];
  float w[8]; dct8(a, w);
#pragma unroll
  for (int k = 0; k < 8; k++) base[t * RPITCH + k] = w[k];   // own row
  __syncwarp();

  // Pass 2 (column-local): D[:,t] = M W[:,t]; quantize; E[:,t] = M deq[:,t].
  float c[8];
#pragma unroll
  for (int k = 0; k < 8; k++) c[k] = base[k * RPITCH + t];
  float d[8]; dct8(c, d);
#pragma unroll
  for (int u = 0; u < 8; u++) {
    float q  = qcol[u];
    float r  = rcol[u];
    // Refined division: t0 + r*(d - t0*q) == d/q rounded-to-nearest (~0.55 ulp).
    float t0 = d[u] * r;
    float e  = fmaf(-t0, q, d[u]);
    float tt = fmaf(e, r, t0);
    d[u] = diff_round(tt) * q;
  }
  float e8[8]; dct8(d, e8);
#pragma unroll
  for (int u = 0; u < 8; u++) base[u * RPITCH + t] = e8[u];  // own column
  __syncwarp();

  // Pass 3 (row-local): rec[t,:] = row t of (E M^T).
  float rr[8];
#pragma unroll
  for (int k = 0; k < 8; k++) rr[k] = base[t * RPITCH + k];
  float o[8]; dct8(rr, o);
#pragma unroll
  for (int k = 0; k < 8; k++) base[t * RPITCH + k] = o[k];   // own row
}

// Shared indexers (block pitch 72, row pitch 9).
__device__ __forceinline__ int yidx(int ly, int lx) {
  return ((ly >> 3) * 8 + (lx >> 3)) * BPITCH + (ly & 7) * RPITCH + (lx & 7);
}
__device__ __forceinline__ int cidx(int ly, int lx) {
  return ((ly >> 3) * 4 + (lx >> 3)) * BPITCH + (ly & 7) * RPITCH + (lx & 7);
}

__global__ __launch_bounds__(THREADS, 7)
void jpeg_fused_kernel(const float* __restrict__ in, float* __restrict__ out, int H, int W) {
  __shared__ float sY[64 * BPITCH];   // 64 Y blocks
  __shared__ float sC[32 * BPITCH];   // 16 Cb blocks then 16 Cr blocks
  __shared__ QTabs sQT;               // staged quant tables (1 KB)

  const int tid = threadIdx.x;
  const int b = blockIdx.z;
  const size_t plane = (size_t)H * W;
  const float* __restrict__ Rp = in + (size_t)b * 3 * plane;
  const float* __restrict__ Gp = Rp + plane;
  const float* __restrict__ Bp = Gp + plane;
  float* __restrict__ Ro = out + (size_t)b * 3 * plane;
  float* __restrict__ Go = Ro + plane;
  float* __restrict__ Bo = Go + plane;

  const int ox = blockIdx.x * 64;
  const int oy = blockIdx.y * 64;

  // Stage quant tables: 64 threads x float4 = 1 KB, coalesced LDG from global.
  if (tid < 64) {
    ((float4*)&sQT)[tid] = ((const float4*)&G_QT)[tid];
  }

  // ---- Load phase: 4x2 pixel units (float4 x 2 rows). 512 units, 2/thread. ----
#pragma unroll
  for (int i = 0; i < 2; i++) {
    const int u = tid + i * THREADS;
    const int ux = u & 15, uy = u >> 4;          // 16 units wide, 32 tall
    const int px = ox + 4 * ux;
    const int py = oy + 2 * uy;
    const size_t o0 = (size_t)py * W + px;
    const size_t o1 = o0 + W;

    float4 r4[2] = { *(const float4*)(Rp + o0), *(const float4*)(Rp + o1) };
    float4 g4[2] = { *(const float4*)(Gp + o0), *(const float4*)(Gp + o1) };
    float4 b4[2] = { *(const float4*)(Bp + o0), *(const float4*)(Bp + o1) };

    const float* rr = (const float*)r4;
    const float* gg = (const float*)g4;
    const float* bb = (const float*)b4;

    float cbs[2] = {0.0f, 0.0f}, crs[2] = {0.0f, 0.0f};
#pragma unroll
    for (int k = 0; k < 8; k++) {               // k = row*4 + col
      const int row = k >> 2, col = k & 3;
      float rv = rr[k] * 255.0f, gv = gg[k] * 255.0f, bv = bb[k] * 255.0f;
      float yv  =  0.299f    * rv + 0.587f    * gv + 0.114f    * bv;
      float cbv = -0.168736f * rv - 0.331264f * gv + 0.5f      * bv;
      float crv =  0.5f      * rv - 0.418688f * gv - 0.081312f * bv;
      const int h = col >> 1;                   // which 2x2 within the 4x2 unit
      cbs[h] += cbv; crs[h] += crv;
      sY[yidx(2 * uy + row, 4 * ux + col)] = yv - 128.0f;  // +/-128 chroma shift cancels
    }
    sC[cidx(uy, 2 * ux)]                   = cbs[0] * 0.25f;
    sC[cidx(uy, 2 * ux + 1)]               = cbs[1] * 0.25f;
    sC[16 * BPITCH + cidx(uy, 2 * ux)]     = crs[0] * 0.25f;
    sC[16 * BPITCH + cidx(uy, 2 * ux + 1)] = crs[1] * 0.25f;
  }
  __syncthreads();

  // ---- Process phase: 32 groups of 8 threads, 3 rounds. ----
  {
    const int t   = tid & 7;
    const int grp = tid >> 3;

    // Hoist this thread's qt column to registers via conflict-free LDS
    // (pattern u*8+t: 8 distinct banks, 4-lane broadcast each).
    float qcol[8], rcol[8];
#pragma unroll
    for (int u = 0; u < 8; u++) {
      qcol[u] = sQT.y.q[u * 8 + t];
      rcol[u] = sQT.y.r[u * 8 + t];
    }
    process_block(sY + grp * BPITCH, t, qcol, rcol);
    process_block(sY + (32 + grp) * BPITCH, t, qcol, rcol);
#pragma unroll
    for (int u = 0; u < 8; u++) {
      qcol[u] = sQT.c.q[u * 8 + t];
      rcol[u] = sQT.c.r[u * 8 + t];
    }
    process_block(sC + grp * BPITCH, t, qcol, rcol);  // grp 0-15 Cb, 16-31 Cr
  }
  __syncthreads();

  // ---- Output phase: 4x2 units, upsample chroma, YCbCr->RGB, saturate. ----
  const float inv255 = 1.0f / 255.0f;
#pragma unroll
  for (int i = 0; i < 2; i++) {
    const int u = tid + i * THREADS;
    const int ux = u & 15, uy = u >> 4;
    const int px = ox + 4 * ux;
    const int py = oy + 2 * uy;
    const size_t o0 = (size_t)py * W + px;
    const size_t o1 = o0 + W;

    float cbv[2], crv[2];
    cbv[0] = sC[cidx(uy, 2 * ux)];
    cbv[1] = sC[cidx(uy, 2 * ux + 1)];
    crv[0] = sC[16 * BPITCH + cidx(uy, 2 * ux)];
    crv[1] = sC[16 * BPITCH + cidx(uy, 2 * ux + 1)];

    float4 r4[2], g4[2], b4[2];
    float* rr = (float*)r4; float* gg = (float*)g4; float* bb = (float*)b4;
#pragma unroll
    for (int k = 0; k < 8; k++) {
      const int row = k >> 2, col = k & 3;
      const int h = col >> 1;
      float yv = sY[yidx(2 * uy + row, 4 * ux + col)] + 128.0f;
      float cb = cbv[h], cr = crv[h];
      // saturate(v*inv255) == clip(clip(v,0,255)/255, 0, 1) (<=1ulp, continuous)
      rr[k] = __saturatef((yv + 1.402f * cr) * inv255);
      gg[k] = __saturatef((yv - 0.344136f * cb - 0.714136f * cr) * inv255);
      bb[k] = __saturatef((yv + 1.772f * cb) * inv255);
    }
    *(float4*)(Ro + o0) = r4[0];
    *(float4*)(Ro + o1) = r4[1];
    *(float4*)(Go + o0) = g4[0];
    *(float4*)(Go + o1) = g4[1];
    *(float4*)(Bo + o0) = b4[0];
    *(float4*)(Bo + o1) = b4[1];
  }
}

extern "C" void kernel_launch(void* const* d_in, const int* in_sizes, int n_in,
                              void* d_out, int out_size) {
  const float* img = (const float*)d_in[0];
  float* out = (float*)d_out;
  const int H = 1024, W = 1024;
  const int B = in_sizes[0] / (3 * H * W);
  dim3 grid(W / 64, H / 64, B);
  dim3 block(THREADS);
  jpeg_fused_kernel<<<grid, block>>>(img, out, H, W);
}

// round 14
// speedup vs baseline: 1.6623x; 1.6623x over previous
#include <cuda_runtime.h>
#include <cstddef>

// ---------------------------------------------------------------------------
// Differentiable JPEG (quality=75), fused, thread-per-row.  [R11 @ half CTA]
// CTA = 64x32 pixel tile = 48 8x8 blocks (32 Y + 8 Cb + 8 Cr), 128 threads.
// 16 groups of 8; each group does one block per round (3 rounds).
// Per block: rec = M ( diff_round( (M (X M^T)) / qt ) * qt ) M^T as 4 identical
// 8-pt butterflies, 2 smem transposes. qt + reciprocal: compile-time tables in
// GLOBAL memory, staged to smem (constant-port divergent-LDC replays killed),
// hoisted to registers once per table via conflict-free LDS.
// Division = rcp-mul + one FMA Newton residual (bit-identical rel_err vs FDIV).
// Shared pitch 9/72 -> conflict-free row AND column access.
// Phase purity: load/output phases are pure streaming (R10/R12: fusing dct
// into memory phases serializes). Occ axis mapped: 40regs/6CTA was optimal at
// 256thr; this keeps the same 42-reg budget at 12 CTAs/SM for finer-grained
// scheduling (12 independent CTAs/SM, half wave-tail quantum).
// ---------------------------------------------------------------------------

#define THREADS 128
#define BPITCH 72
#define RPITCH 9

// ---- Compile-time scaled quant tables (quality=75 -> s=50 -> t=(q+1)/2). ----
struct QTab { float q[64]; float r[64]; };
struct QTabs { QTab y; QTab c; };

constexpr QTab make_tab(const int (&b)[64]) {
  QTab t{};
  for (int i = 0; i < 64; i++) {
    int n = b[i] + 1;                       // scaled numerator: t = n/2 exactly
    double v = 0.0;
    if ((n & 1) == 0) {
      v = (double)(n / 2);                  // integer -> diff_round is identity
    } else {
      long k = n / 2;                       // t = k + 0.5 (exact tie)
      double tt = (double)k + 0.5;
      double rr = ((k & 1) == 0) ? (double)k : (double)(k + 1);  // half-to-even
      double d  = tt - rr;
      v = rr + d * d * d;                   // diff_round
    }
    if (v < 1.0) v = 1.0;
    if (v > 255.0) v = 255.0;
    t.q[i] = (float)v;                      // exact (values are k + m/8)
    t.r[i] = (float)(1.0 / (double)((float)v));  // correctly-rounded fp32 recip
  }
  return t;
}

constexpr int QY_B[64] = {
  16,11,10,16,24,40,51,61,
  12,12,14,19,26,58,60,55,
  14,13,16,24,40,57,69,56,
  14,17,22,29,51,87,80,62,
  18,22,37,56,68,109,103,77,
  24,35,55,64,81,104,113,92,
  49,64,78,87,103,121,120,101,
  72,92,95,98,112,100,103,99 };

constexpr int QC_B[64] = {
  17,18,24,47,99,99,99,99,
  18,21,26,66,99,99,99,99,
  24,26,56,99,99,99,99,99,
  47,66,99,99,99,99,99,99,
  99,99,99,99,99,99,99,99,
  99,99,99,99,99,99,99,99,
  99,99,99,99,99,99,99,99,
  99,99,99,99,99,99,99,99 };

// Global memory (not __constant__): divergent LDC replays on the half-rate
// constant port serialized R7/R8.
__device__ const QTabs G_QT = { make_tab(QY_B), make_tab(QC_B) };

__device__ __forceinline__ float diff_round(float x) {
  float r = rintf(x);           // round half to even, matches jnp.round
  float d = x - r;
  return fmaf(d * d, d, r);
}

// out[u] = sum_k M[u,k] a[k] -- 8-pt DCT-II via even/odd butterfly (~36 ops).
__device__ __forceinline__ void dct8(const float* __restrict__ a, float* __restrict__ out) {
  const float S  = 0.3535533905932738f;
  const float A  = 0.4619397662556434f, B  = 0.1913417161825449f;
  const float c1 = 0.4903926402016152f, c3 = 0.4157348061512726f;
  const float c5 = 0.2777851165098011f, c7 = 0.0975451610080641f;
  float e0 = a[0] + a[7], e1 = a[1] + a[6], e2 = a[2] + a[5], e3 = a[3] + a[4];
  float o0 = a[0] - a[7], o1 = a[1] - a[6], o2 = a[2] - a[5], o3 = a[3] - a[4];
  float q0 = e0 + e3, q1 = e1 + e2;
  float r0 = e0 - e3, r1 = e1 - e2;
  out[0] = S * (q0 + q1);
  out[4] = S * (q0 - q1);
  out[2] = fmaf(A, r0,  B * r1);
  out[6] = fmaf(B, r0, -A * r1);
  out[1] = fmaf(c1, o0, fmaf( c3, o1, fmaf( c5, o2,  c7 * o3)));
  out[3] = fmaf(c3, o0, fmaf(-c7, o1, fmaf(-c1, o2, -c5 * o3)));
  out[5] = fmaf(c5, o0, fmaf(-c1, o1, fmaf( c7, o2,  c3 * o3)));
  out[7] = fmaf(c7, o0, fmaf(-c5, o1, fmaf( c3, o2, -c1 * o3)));
}

// Full block pipeline, thread t of an 8-thread group. Only 2 syncwarps.
// qcol/rcol: this thread's quant column (qt[u][t]) and its fp32 reciprocal.
__device__ __forceinline__ void process_block(float* __restrict__ base, int t,
                                              const float* __restrict__ qcol,
                                              const float* __restrict__ rcol) {
  // Pass 1 (row-local): W[t,:] = row t of (X M^T).
  float a[8];
#pragma unroll
  for (int k = 0; k < 8; k++) a[k] = base[t * RPITCH + k];
  float w[8]; dct8(a, w);
#pragma unroll
  for (int k = 0; k < 8; k++) base[t * RPITCH + k] = w[k];   // own row
  __syncwarp();

  // Pass 2 (column-local): D[:,t] = M W[:,t]; quantize; E[:,t] = M deq[:,t].
  float c[8];
#pragma unroll
  for (int k = 0; k < 8; k++) c[k] = base[k * RPITCH + t];
  float d[8]; dct8(c, d);
#pragma unroll
  for (int u = 0; u < 8; u++) {
    float q  = qcol[u];
    float r  = rcol[u];
    // Refined division: t0 + r*(d - t0*q) == d/q rounded-to-nearest (~0.55 ulp).
    float t0 = d[u] * r;
    float e  = fmaf(-t0, q, d[u]);
    float tt = fmaf(e, r, t0);
    d[u] = diff_round(tt) * q;
  }
  float e8[8]; dct8(d, e8);
#pragma unroll
  for (int u = 0; u < 8; u++) base[u * RPITCH + t] = e8[u];  // own column
  __syncwarp();

  // Pass 3 (row-local): rec[t,:] = row t of (E M^T).
  float rr[8];
#pragma unroll
  for (int k = 0; k < 8; k++) rr[k] = base[t * RPITCH + k];
  float o[8]; dct8(rr, o);
#pragma unroll
  for (int k = 0; k < 8; k++) base[t * RPITCH + k] = o[k];   // own row
}

// Shared indexers (block pitch 72, row pitch 9).
// Y plane: 64x32 px = 8 x 4 blocks. Chroma plane: 32x16 px = 4 x 2 blocks.
__device__ __forceinline__ int yidx(int ly, int lx) {
  return ((ly >> 3) * 8 + (lx >> 3)) * BPITCH + (ly & 7) * RPITCH + (lx & 7);
}
__device__ __forceinline__ int cidx(int ly, int lx) {
  return ((ly >> 3) * 4 + (lx >> 3)) * BPITCH + (ly & 7) * RPITCH + (lx & 7);
}

__global__ __launch_bounds__(THREADS, 12)
void jpeg_fused_kernel(const float* __restrict__ in, float* __restrict__ out, int H, int W) {
  __shared__ float sY[32 * BPITCH];   // 32 Y blocks
  __shared__ float sC[16 * BPITCH];   // 8 Cb blocks then 8 Cr blocks
  __shared__ QTabs sQT;               // staged quant tables (1 KB)

  const int tid = threadIdx.x;
  const int b = blockIdx.z;
  const size_t plane = (size_t)H * W;
  const float* __restrict__ Rp = in + (size_t)b * 3 * plane;
  const float* __restrict__ Gp = Rp + plane;
  const float* __restrict__ Bp = Gp + plane;
  float* __restrict__ Ro = out + (size_t)b * 3 * plane;
  float* __restrict__ Go = Ro + plane;
  float* __restrict__ Bo = Go + plane;

  const int ox = blockIdx.x * 64;
  const int oy = blockIdx.y * 32;

  // Stage quant tables: 64 threads x float4 = 1 KB, coalesced LDG from global.
  if (tid < 64) {
    ((float4*)&sQT)[tid] = ((const float4*)&G_QT)[tid];
  }

  // ---- Load phase: 4x2 pixel units (float4 x 2 rows). 256 units, 2/thread. ----
#pragma unroll
  for (int i = 0; i < 2; i++) {
    const int u = tid + i * THREADS;
    const int ux = u & 15, uy = u >> 4;          // 16 units wide, 16 tall
    const int px = ox + 4 * ux;
    const int py = oy + 2 * uy;
    const size_t o0 = (size_t)py * W + px;
    const size_t o1 = o0 + W;

    float4 r4[2] = { *(const float4*)(Rp + o0), *(const float4*)(Rp + o1) };
    float4 g4[2] = { *(const float4*)(Gp + o0), *(const float4*)(Gp + o1) };
    float4 b4[2] = { *(const float4*)(Bp + o0), *(const float4*)(Bp + o1) };

    const float* rr = (const float*)r4;
    const float* gg = (const float*)g4;
    const float* bb = (const float*)b4;

    float cbs[2] = {0.0f, 0.0f}, crs[2] = {0.0f, 0.0f};
#pragma unroll
    for (int k = 0; k < 8; k++) {               // k = row*4 + col
      const int row = k >> 2, col = k & 3;
      float rv = rr[k] * 255.0f, gv = gg[k] * 255.0f, bv = bb[k] * 255.0f;
      float yv  =  0.299f    * rv + 0.587f    * gv + 0.114f    * bv;
      float cbv = -0.168736f * rv - 0.331264f * gv + 0.5f      * bv;
      float crv =  0.5f      * rv - 0.418688f * gv - 0.081312f * bv;
      const int h = col >> 1;                   // which 2x2 within the 4x2 unit
      cbs[h] += cbv; crs[h] += crv;
      sY[yidx(2 * uy + row, 4 * ux + col)] = yv - 128.0f;  // +/-128 chroma shift cancels
    }
    sC[cidx(uy, 2 * ux)]                  = cbs[0] * 0.25f;
    sC[cidx(uy, 2 * ux + 1)]              = cbs[1] * 0.25f;
    sC[8 * BPITCH + cidx(uy, 2 * ux)]     = crs[0] * 0.25f;
    sC[8 * BPITCH + cidx(uy, 2 * ux + 1)] = crs[1] * 0.25f;
  }
  __syncthreads();

  // ---- Process phase: 16 groups of 8 threads, 3 rounds. ----
  {
    const int t   = tid & 7;
    const int grp = tid >> 3;                   // 0..15

    // Hoist this thread's qt column to registers via conflict-free LDS
    // (pattern u*8+t: 8 distinct banks, 4-lane broadcast each).
    float qcol[8], rcol[8];
#pragma unroll
    for (int u = 0; u < 8; u++) {
      qcol[u] = sQT.y.q[u * 8 + t];
      rcol[u] = sQT.y.r[u * 8 + t];
    }
    process_block(sY + grp * BPITCH, t, qcol, rcol);
    process_block(sY + (16 + grp) * BPITCH, t, qcol, rcol);
#pragma unroll
    for (int u = 0; u < 8; u++) {
      qcol[u] = sQT.c.q[u * 8 + t];
      rcol[u] = sQT.c.r[u * 8 + t];
    }
    process_block(sC + grp * BPITCH, t, qcol, rcol);  // grp 0-7 Cb, 8-15 Cr
  }
  __syncthreads();

  // ---- Output phase: 4x2 units, upsample chroma, YCbCr->RGB, saturate. ----
  const float inv255 = 1.0f / 255.0f;
#pragma unroll
  for (int i = 0; i < 2; i++) {
    const int u = tid + i * THREADS;
    const int ux = u & 15, uy = u >> 4;
    const int px = ox + 4 * ux;
    const int py = oy + 2 * uy;
    const size_t o0 = (size_t)py * W + px;
    const size_t o1 = o0 + W;

    float cbv[2], crv[2];
    cbv[0] = sC[cidx(uy, 2 * ux)];
    cbv[1] = sC[cidx(uy, 2 * ux + 1)];
    crv[0] = sC[8 * BPITCH + cidx(uy, 2 * ux)];
    crv[1] = sC[8 * BPITCH + cidx(uy, 2 * ux + 1)];

    float4 r4[2], g4[2], b4[2];
    float* rr = (float*)r4; float* gg = (float*)g4; float* bb = (float*)b4;
#pragma unroll
    for (int k = 0; k < 8; k++) {
      const int row = k >> 2, col = k & 3;
      const int h = col >> 1;
      float yv = sY[yidx(2 * uy + row, 4 * ux + col)] + 128.0f;
      float cb = cbv[h], cr = crv[h];
      // saturate(v*inv255) == clip(clip(v,0,255)/255, 0, 1) (<=1ulp, continuous)
      rr[k] = __saturatef((yv + 1.402f * cr) * inv255);
      gg[k] = __saturatef((yv - 0.344136f * cb - 0.714136f * cr) * inv255);
      bb[k] = __saturatef((yv + 1.772f * cb) * inv255);
    }
    *(float4*)(Ro + o0) = r4[0];
    *(float4*)(Ro + o1) = r4[1];
    *(float4*)(Go + o0) = g4[0];
    *(float4*)(Go + o1) = g4[1];
    *(float4*)(Bo + o0) = b4[0];
    *(float4*)(Bo + o1) = b4[1];
  }
}

extern "C" void kernel_launch(void* const* d_in, const int* in_sizes, int n_in,
                              void* d_out, int out_size) {
  const float* img = (const float*)d_in[0];
  float* out = (float*)d_out;
  const int H = 1024, W = 1024;
  const int B = in_sizes[0] / (3 * H * W);
  dim3 grid(W / 64, H / 32, B);
  dim3 block(THREADS);
  jpeg_fused_kernel<<<grid, block>>>(img, out, H, W);
}